// round 4
// baseline (speedup 1.0000x reference)
#include <cuda_runtime.h>
#include <cstdint>

// ConstituencyMFVI: B=8, N=192, 3 mean-field iterations.
// q[b,i,j] = s_span[b,i,j] + (j>i) * sum_{k != i, k != j} sigmoid(q[b,i,k]) * s_pair[b,i,j,k]
// out = sigmoid(q).
//
//  - mask = (j > i) analytic; rows j <= i of s_pair never touched (113MB total HBM).
//  - thread j owns row j. Low k-half [0,96) ends in registers (24 x float4),
//    high k-half [96,192) stays in SMEM (stride 100 -> conflict-free vec4).
//  - loads split into 6 x 32-col blocks (one 128B line per row, coalesced
//    cp.async). Pipeline keeps >=2 groups in flight at all times, and
//    iteration 1 (sigma0 = sigmoid(s_span), known upfront) is fused into the
//    load stream: low blocks FMA'd during reg-copy, high blocks FMA'd as each
//    group retires. Only iterations 2-3 run after the load completes.

namespace {
constexpr int NN      = 192;
constexpr int BB      = 8;
constexpr int PADH    = 100;   // SMEM row stride (100 % 8 == 4 -> conflict-free LDS.128)
constexpr int THREADS = 192;
constexpr int BW      = 32;    // cols per load block (= one 128B line per row)
}

__device__ __forceinline__ float sigmoidf(float x) {
    return 1.0f / (1.0f + __expf(-x));
}

template <int N>
__device__ __forceinline__ void cp_wait() {
    asm volatile("cp.async.wait_group %0;\n" :: "n"(N));
}

__global__ __launch_bounds__(THREADS, 2)
void mfvi_kernel(const float* __restrict__ s_span,
                 const float* __restrict__ s_pair,
                 float* __restrict__ out)
{
    extern __shared__ float sm[];
    float* buf = sm;               // [192][PADH]; holds low half, then high half
    float* sig = sm + NN * PADH;   // [192]

    const int i = blockIdx.x;
    const int b = blockIdx.y;
    const int j = threadIdx.x;
    const int R   = NN - 1 - i;    // active rows (j > i)
    const int nch = R * 8;         // 16B chunks per 32-col block

    const size_t rowbase = (size_t)(b * NN + i);
    const float* gP = s_pair + rowbase * (size_t)(NN * NN);

    const uint32_t sbuf = (uint32_t)__cvta_generic_to_shared(buf);

    // ---- issue low-half blocks g=0,1,2 (cols 32g..32g+31), one group each ----
    #pragma unroll
    for (int g = 0; g < 3; g++) {
        for (int c = j; c < nch; c += THREADS) {
            int row = i + 1 + (c >> 3);
            int col = g * BW + ((c & 7) << 2);
            uint32_t dst = sbuf + (uint32_t)(row * PADH + col) * 4u;
            const float* src = gP + (size_t)row * NN + col;
            asm volatile("cp.async.cg.shared.global [%0], [%1], 16;\n" :: "r"(dst), "l"(src));
        }
        asm volatile("cp.async.commit_group;\n");
    }

    // scalar setup overlaps the stream
    const float s = s_span[rowbase * NN + j];
    float q = s;
    sig[j] = sigmoidf(s);          // sigma0, known before any tile data

    float4 r[24];
    float ax = 0.f, ay = 0.f, az = 0.f, aw = 0.f;
    const float4* sig4 = reinterpret_cast<const float4*>(sig);

    // ---- low blocks: retire -> regs + iter-1 partial -> refill with high block ----
    #pragma unroll
    for (int g = 0; g < 3; g++) {
        cp_wait<2>();              // oldest outstanding group (low block g) done
        __syncthreads();           // visible CTA-wide (also publishes sig0 on g=0)
        if (j > i) {
            float* myrow = buf + j * PADH + g * BW;
            if ((i >> 5) == g)            myrow[i & 31] = 0.0f;   // k == i (i<96 here)
            if (j < 96 && (j >> 5) == g)  myrow[j & 31] = 0.0f;   // k == j
            const float4* row4 = reinterpret_cast<const float4*>(myrow);
            #pragma unroll
            for (int c = 0; c < 8; c++) {
                float4 p = row4[c];
                r[g * 8 + c] = p;
                float4 sg = sig4[g * 8 + c];
                ax = fmaf(p.x, sg.x, ax);
                ay = fmaf(p.y, sg.y, ay);
                az = fmaf(p.z, sg.z, az);
                aw = fmaf(p.w, sg.w, aw);
            }
        }
        __syncthreads();           // all reg copies of block g done -> safe to overwrite
        for (int c = j; c < nch; c += THREADS) {   // high block g -> same cols
            int row = i + 1 + (c >> 3);
            int col = g * BW + ((c & 7) << 2);
            uint32_t dst = sbuf + (uint32_t)(row * PADH + col) * 4u;
            const float* src = gP + (size_t)row * NN + 96 + col;
            asm volatile("cp.async.cg.shared.global [%0], [%1], 16;\n" :: "r"(dst), "l"(src));
        }
        asm volatile("cp.async.commit_group;\n");
    }

    // ---- high blocks: retire progressively, iter-1 partial from SMEM ----
    #pragma unroll
    for (int h = 0; h < 3; h++) {
        if (h == 0) cp_wait<2>(); else if (h == 1) cp_wait<1>(); else cp_wait<0>();
        __syncthreads();
        if (j > i) {
            float* myrow = buf + j * PADH + h * BW;
            int ih = i - 96, jh = j - 96;
            if (ih >= 0 && (ih >> 5) == h) myrow[ih & 31] = 0.0f;  // k == i (>=96)
            if (jh >= 0 && (jh >> 5) == h) myrow[jh & 31] = 0.0f;  // k == j (>=96)
            const float4* row4 = reinterpret_cast<const float4*>(myrow);
            #pragma unroll
            for (int c = 0; c < 8; c++) {
                float4 p  = row4[c];
                float4 sg = sig4[24 + h * 8 + c];
                ax = fmaf(p.x, sg.x, ax);
                ay = fmaf(p.y, sg.y, ay);
                az = fmaf(p.z, sg.z, az);
                aw = fmaf(p.w, sg.w, aw);
            }
        }
    }

    // iteration 1 result
    if (j > i) q = s + ((ax + ay) + (az + aw));
    __syncthreads();               // all iter-1 reads of sig0 done
    if (j > i) sig[j] = sigmoidf(q);
    __syncthreads();

    // ---- iterations 2 and 3: tile fully resident (regs + SMEM) ----
    const float4* row4 = reinterpret_cast<const float4*>(buf + j * PADH);
    #pragma unroll 1
    for (int it = 0; it < 2; it++) {
        if (j > i) {
            float bx = 0.f, by = 0.f, bz = 0.f, bw = 0.f;
            #pragma unroll
            for (int c = 0; c < 24; c++) {           // low half from regs
                float4 sg = sig4[c];
                bx = fmaf(r[c].x, sg.x, bx);
                by = fmaf(r[c].y, sg.y, by);
                bz = fmaf(r[c].z, sg.z, bz);
                bw = fmaf(r[c].w, sg.w, bw);
            }
            #pragma unroll
            for (int c = 0; c < 24; c++) {           // high half from SMEM
                float4 p  = row4[c];
                float4 sg = sig4[24 + c];
                bx = fmaf(p.x, sg.x, bx);
                by = fmaf(p.y, sg.y, by);
                bz = fmaf(p.z, sg.z, bz);
                bw = fmaf(p.w, sg.w, bw);
            }
            q = s + ((bx + by) + (bz + bw));
        }
        if (it == 0) {
            __syncthreads();
            if (j > i) sig[j] = sigmoidf(q);
            __syncthreads();
        }
    }

    out[rowbase * NN + j] = sigmoidf(q);
}

extern "C" void kernel_launch(void* const* d_in, const int* in_sizes, int n_in,
                              void* d_out, int out_size)
{
    const float* s_span = (const float*)d_in[0];
    const float* s_pair = (const float*)d_in[1];
    float* out = (float*)d_out;

    size_t smem = (size_t)(NN * PADH + NN) * sizeof(float);  // ~77.6 KB -> 2 CTAs/SM
    cudaFuncSetAttribute(mfvi_kernel,
                         cudaFuncAttributeMaxDynamicSharedMemorySize, (int)smem);

    dim3 grid(NN, BB);   // big tiles (small i) first
    mfvi_kernel<<<grid, THREADS, smem>>>(s_span, s_pair, out);
}